// round 14
// baseline (speedup 1.0000x reference)
#include <cuda_runtime.h>
#include <cuda_bf16.h>
#include <cstdint>

// GCN sparse aggregation: out[r,:] += vals[e] * embeds[cols[e],:]
// N=100000 nodes, E=1600000 edges, D=64, fp32.
//
// Round 13: r12 pipeline (best @74.4) + aggregate instruction-diet:
//   - placeB stores PRE-SCALED col offsets (col*32 float2-elems) -> 1 IMAD/gather
//   - scan pads every row to EVEN length (pad = {0,0.0f} -> contributes 0),
//     so rows are 16B-aligned and aggregate loads TWO edges per LDG.128
//   - unroll 8 edges/iter
// Pipeline: rank -> lookback scan (padded, writes pad slots) -> placeB -> aggregate.

#define D_FEAT 64
#define NV 100000
#define NE 1600000
#define SCAN_BS 512
#define NB ((NV + SCAN_BS - 1) / SCAN_BS)   // 196

__device__ int  g_count[NV];          // zero at load; scan restores 0 each run
__device__ int  g_rowstart[NV + 1];   // padded-even prefix
__device__ int  g_rank[NE];
__device__ int2 g_edge[NE + NV];      // {col*32, val_bits}; even-padded rows
__device__ unsigned long long g_desc[NB];   // lookback {flag,value}; placeB resets

// ---- memory helpers ----
__device__ __forceinline__ int4 ldcs_int4(const int4* p) {
    int4 v;
    asm volatile("ld.global.cs.v4.s32 {%0,%1,%2,%3}, [%4];"
                 : "=r"(v.x), "=r"(v.y), "=r"(v.z), "=r"(v.w) : "l"(p));
    return v;
}
__device__ __forceinline__ float4 ldcs_float4(const float4* p) {
    float4 v;
    asm volatile("ld.global.cs.v4.f32 {%0,%1,%2,%3}, [%4];"
                 : "=f"(v.x), "=f"(v.y), "=f"(v.z), "=f"(v.w) : "l"(p));
    return v;
}
__device__ __forceinline__ void stcs_float2(float2* p, float2 v) {
    asm volatile("st.global.cs.v2.f32 [%0], {%1,%2};"
                 :: "l"(p), "f"(v.x), "f"(v.y) : "memory");
}
__device__ __forceinline__ void st_rel_u64(unsigned long long* p, unsigned long long v) {
    asm volatile("st.relaxed.gpu.global.u64 [%0], %1;" :: "l"(p), "l"(v) : "memory");
}
__device__ __forceinline__ unsigned long long ld_rel_u64(const unsigned long long* p) {
    unsigned long long v;
    asm volatile("ld.relaxed.gpu.global.u64 %0, [%1];" : "=l"(v) : "l"(p) : "memory");
    return v;
}

// ---- 1) rank: histogram + slot assignment ----
__global__ void __launch_bounds__(256) rank_kernel(
    const int4* __restrict__ rows4, int n_quads)
{
    int t = blockIdx.x * blockDim.x + threadIdx.x;
    if (t >= n_quads) return;
    int4 r = __ldg(&rows4[t]);               // default: placeB re-reads rows
    int k0 = atomicAdd(&g_count[r.x], 1);
    int k1 = atomicAdd(&g_count[r.y], 1);
    int k2 = atomicAdd(&g_count[r.z], 1);
    int k3 = atomicAdd(&g_count[r.w], 1);
    *reinterpret_cast<int4*>(&g_rank[t * 4]) = make_int4(k0, k1, k2, k3);  // hot
}

__global__ void __launch_bounds__(256) rank_tail_kernel(
    const int* __restrict__ rows, int start, int n_edges)
{
    int e = start + blockIdx.x * blockDim.x + threadIdx.x;
    if (e < n_edges) g_rank[e] = atomicAdd(&g_count[rows[e]], 1);
}

// ---- 2) single-pass decoupled-lookback scan over EVEN-PADDED counts ----
__global__ void __launch_bounds__(SCAN_BS) scan_kernel(int n_nodes) {
    __shared__ int warp_sums[16];
    __shared__ int s_excl;
    int b    = blockIdx.x;
    int tid  = threadIdx.x;
    int lane = tid & 31;
    int wid  = tid >> 5;
    int g    = b * SCAN_BS + tid;

    int v = 0;
    if (g < n_nodes) {
        v = g_count[g];
        g_count[g] = 0;                      // invariant for next replay
    }
    int vp = (v + 1) & ~1;                   // padded-even length

    int incl = vp;
    #pragma unroll
    for (int o = 1; o < 32; o <<= 1) {
        int n = __shfl_up_sync(0xffffffffu, incl, o);
        if (lane >= o) incl += n;
    }
    if (lane == 31) warp_sums[wid] = incl;
    __syncthreads();

    if (wid == 0) {
        int ws = (lane < 16) ? warp_sums[lane] : 0;
        #pragma unroll
        for (int o = 1; o < 32; o <<= 1) {
            int n = __shfl_up_sync(0xffffffffu, ws, o);
            if (lane >= o) ws += n;
        }
        if (lane < 16) warp_sums[lane] = ws;
    }
    __syncthreads();

    int block_total = warp_sums[15];
    int thread_excl = ((wid == 0) ? 0 : warp_sums[wid - 1]) + incl - vp;

    if (wid == 0) {
        int sum = 0;
        if (b == 0) {
            if (lane == 0)
                st_rel_u64(&g_desc[0], (2ULL << 32) | (unsigned)block_total);
        } else {
            if (lane == 0)
                st_rel_u64(&g_desc[b], (1ULL << 32) | (unsigned)block_total);
            int base = b;
            bool done = false;
            while (!done) {
                int idx = base - 32 + lane;
                unsigned f = 1;
                int val = 0;
                if (idx >= 0) {
                    unsigned long long dd;
                    do {
                        dd = ld_rel_u64(&g_desc[idx]);
                        f = (unsigned)(dd >> 32);
                    } while (f == 0);
                    val = (int)(unsigned)dd;
                }
                unsigned m2 = __ballot_sync(0xffffffffu, f == 2u);
                int P = m2 ? (31 - __clz(m2)) : -1;
                if (P >= 0 && lane < P) val = 0;
                #pragma unroll
                for (int o = 16; o; o >>= 1)
                    val += __shfl_xor_sync(0xffffffffu, val, o);
                sum += val;
                if (P >= 0) done = true; else base -= 32;
            }
            if (lane == 0)
                st_rel_u64(&g_desc[b], (2ULL << 32) | (unsigned)(sum + block_total));
        }
        if (lane == 0) s_excl = sum;
    }
    __syncthreads();

    int excl = s_excl;
    if (g < n_nodes) {
        int rs = excl + thread_excl;
        g_rowstart[g] = rs;
        if (v & 1) g_edge[rs + v] = make_int2(0, 0);   // pad: 0 * embeds[0] = 0
        if (g == n_nodes - 1) g_rowstart[n_nodes] = rs + vp;
    }
}

// ---- 3) placeB: atomic-free scatter; stores PRE-SCALED col offsets ----
__global__ void __launch_bounds__(256) placeB_kernel(
    const int4*   __restrict__ rows4,
    const int4*   __restrict__ cols4,
    const float4* __restrict__ vals4,
    int n_quads)
{
    int t = blockIdx.x * blockDim.x + threadIdx.x;
    if (t < NB) g_desc[t] = 0;               // reset lookback state for next replay
    if (t >= n_quads) return;

    int4   r = ldcs_int4(&rows4[t]);         // last touch
    int4   c = ldcs_int4(&cols4[t]);         // last touch
    float4 v = ldcs_float4(&vals4[t]);       // last touch
    int4   k = ldcs_int4(reinterpret_cast<const int4*>(&g_rank[t * 4]));  // last touch

    int s0 = __ldg(&g_rowstart[r.x]);
    int s1 = __ldg(&g_rowstart[r.y]);
    int s2 = __ldg(&g_rowstart[r.z]);
    int s3 = __ldg(&g_rowstart[r.w]);

    g_edge[s0 + k.x] = make_int2(c.x << 5, __float_as_int(v.x));   // col*32
    g_edge[s1 + k.y] = make_int2(c.y << 5, __float_as_int(v.y));
    g_edge[s2 + k.z] = make_int2(c.z << 5, __float_as_int(v.z));
    g_edge[s3 + k.w] = make_int2(c.w << 5, __float_as_int(v.w));
}

__global__ void __launch_bounds__(256) placeB_tail_kernel(
    const int*   __restrict__ rows,
    const int*   __restrict__ cols,
    const float* __restrict__ vals,
    int start, int n_edges)
{
    int e = start + blockIdx.x * blockDim.x + threadIdx.x;
    if (e >= n_edges) return;
    int r = rows[e];
    int pos = __ldg(&g_rowstart[r]) + g_rank[e];
    g_edge[pos] = make_int2(cols[e] << 5, __float_as_int(vals[e]));
}

// ---- 4) aggregate: warp/node, 2 edges per LDG.128, 1 IMAD per gather ----
__global__ void __launch_bounds__(256) aggregate_kernel(
    const float2* __restrict__ embeds2,   // [NV, 32] float2
    float2*       __restrict__ out2,      // [NV, 32] float2
    int n_nodes)
{
    int w    = (blockIdx.x * blockDim.x + threadIdx.x) >> 5;
    int lane = threadIdx.x & 31;
    if (w >= n_nodes) return;

    int i   = g_rowstart[w];      // even -> 16B aligned
    int end = g_rowstart[w + 1];  // even
    int pairs = (end - i) >> 1;

    const int4*   ep = reinterpret_cast<const int4*>(g_edge + i);
    const float2* eb = embeds2 + lane;    // lane offset hoisted out of the loop

    float ax = 0.f, ay = 0.f;
    int j = 0;
    for (; j + 3 < pairs; j += 4) {       // 8 edges per iteration
        int4 a = __ldg(&ep[j]);
        int4 b = __ldg(&ep[j + 1]);
        int4 c = __ldg(&ep[j + 2]);
        int4 d = __ldg(&ep[j + 3]);
        float2 x0 = __ldg(eb + a.x);
        float2 x1 = __ldg(eb + a.z);
        float2 x2 = __ldg(eb + b.x);
        float2 x3 = __ldg(eb + b.z);
        float2 x4 = __ldg(eb + c.x);
        float2 x5 = __ldg(eb + c.z);
        float2 x6 = __ldg(eb + d.x);
        float2 x7 = __ldg(eb + d.z);
        float v0 = __int_as_float(a.y);
        float v1 = __int_as_float(a.w);
        float v2 = __int_as_float(b.y);
        float v3 = __int_as_float(b.w);
        float v4 = __int_as_float(c.y);
        float v5 = __int_as_float(c.w);
        float v6 = __int_as_float(d.y);
        float v7 = __int_as_float(d.w);
        ax += v0 * x0.x; ay += v0 * x0.y;
        ax += v1 * x1.x; ay += v1 * x1.y;
        ax += v2 * x2.x; ay += v2 * x2.y;
        ax += v3 * x3.x; ay += v3 * x3.y;
        ax += v4 * x4.x; ay += v4 * x4.y;
        ax += v5 * x5.x; ay += v5 * x5.y;
        ax += v6 * x6.x; ay += v6 * x6.y;
        ax += v7 * x7.x; ay += v7 * x7.y;
    }
    for (; j < pairs; ++j) {              // 2 edges per iteration
        int4 a = __ldg(&ep[j]);
        float2 x0 = __ldg(eb + a.x);
        float2 x1 = __ldg(eb + a.z);
        float v0 = __int_as_float(a.y);
        float v1 = __int_as_float(a.w);
        ax += v0 * x0.x; ay += v0 * x0.y;
        ax += v1 * x1.x; ay += v1 * x1.y;
    }
    stcs_float2(&out2[(size_t)w * 32 + lane], make_float2(ax, ay));  // last touch
}

extern "C" void kernel_launch(void* const* d_in, const int* in_sizes, int n_in,
                              void* d_out, int out_size)
{
    const int*   rows   = (const int*)d_in[0];
    const int*   cols   = (const int*)d_in[1];
    const float* vals   = (const float*)d_in[2];
    const float* embeds = (const float*)d_in[3];
    int n_edges = in_sizes[0];
    if (n_edges > NE) n_edges = NE;
    int n_nodes = out_size / D_FEAT;
    if (n_nodes > NV) n_nodes = NV;

    float* out = (float*)d_out;

    int n_quads   = n_edges >> 2;
    int quad_tail = n_quads << 2;

    {   // 1) rank
        int blocks = (n_quads + 255) / 256;
        rank_kernel<<<blocks, 256>>>((const int4*)rows, n_quads);
        if (quad_tail < n_edges) {
            int tail = n_edges - quad_tail;
            rank_tail_kernel<<<(tail + 255) / 256, 256>>>(rows, quad_tail, n_edges);
        }
    }
    {   // 2) single-pass scan (padded-even; writes pad slots)
        scan_kernel<<<NB, SCAN_BS>>>(n_nodes);
    }
    {   // 3) placeB
        int blocks = (n_quads + 255) / 256;
        placeB_kernel<<<blocks, 256>>>(
            (const int4*)rows, (const int4*)cols, (const float4*)vals, n_quads);
        if (quad_tail < n_edges) {
            int tail = n_edges - quad_tail;
            placeB_tail_kernel<<<(tail + 255) / 256, 256>>>(
                rows, cols, vals, quad_tail, n_edges);
        }
    }
    {   // 4) aggregate
        long long total = (long long)n_nodes * 32;
        int blocks = (int)((total + 255) / 256);
        aggregate_kernel<<<blocks, 256>>>(
            (const float2*)embeds, (float2*)out, n_nodes);
    }
}

// round 15
// speedup vs baseline: 1.0571x; 1.0571x over previous
#include <cuda_runtime.h>
#include <cuda_bf16.h>
#include <cstdint>

// GCN sparse aggregation: out[r,:] += vals[e] * embeds[cols[e],:]
// N=100000 nodes, E=1600000 edges, D=64, fp32.
//
// Round 14: r12 pipeline (best @74.4) with a re-shaped aggregate:
//   2 nodes per WARP — each 16-lane half owns one node, each lane owns a
//   float4 (4 features) of the D=64 row. Per loop iteration the warp covers
//   2 edges with the instruction count r12 spent on 1 (issue-bound fix).
//   placeB stores pre-scaled col*16 so the gather address is one IADD.
// Pipeline: rank -> single-pass lookback scan -> placeB -> aggregate.

#define D_FEAT 64
#define NV 100000
#define NE 1600000
#define SCAN_BS 512
#define NB ((NV + SCAN_BS - 1) / SCAN_BS)   // 196

__device__ int  g_count[NV];        // zero at load; scan restores 0 each run
__device__ int  g_rowstart[NV + 1];
__device__ int  g_rank[NE];
__device__ int2 g_edge[NE];         // {col*16, val_bits}, grouped by row
__device__ unsigned long long g_desc[NB];   // lookback {flag,value}; placeB resets

// ---- memory helpers ----
__device__ __forceinline__ int4 ldcs_int4(const int4* p) {
    int4 v;
    asm volatile("ld.global.cs.v4.s32 {%0,%1,%2,%3}, [%4];"
                 : "=r"(v.x), "=r"(v.y), "=r"(v.z), "=r"(v.w) : "l"(p));
    return v;
}
__device__ __forceinline__ float4 ldcs_float4(const float4* p) {
    float4 v;
    asm volatile("ld.global.cs.v4.f32 {%0,%1,%2,%3}, [%4];"
                 : "=f"(v.x), "=f"(v.y), "=f"(v.z), "=f"(v.w) : "l"(p));
    return v;
}
__device__ __forceinline__ void stcs_float4(float4* p, float4 v) {
    asm volatile("st.global.cs.v4.f32 [%0], {%1,%2,%3,%4};"
                 :: "l"(p), "f"(v.x), "f"(v.y), "f"(v.z), "f"(v.w) : "memory");
}
__device__ __forceinline__ void st_rel_u64(unsigned long long* p, unsigned long long v) {
    asm volatile("st.relaxed.gpu.global.u64 [%0], %1;" :: "l"(p), "l"(v) : "memory");
}
__device__ __forceinline__ unsigned long long ld_rel_u64(const unsigned long long* p) {
    unsigned long long v;
    asm volatile("ld.relaxed.gpu.global.u64 %0, [%1];" : "=l"(v) : "l"(p) : "memory");
    return v;
}

// ---- 1) rank: histogram + slot assignment ----
__global__ void __launch_bounds__(256) rank_kernel(
    const int4* __restrict__ rows4, int n_quads)
{
    int t = blockIdx.x * blockDim.x + threadIdx.x;
    if (t >= n_quads) return;
    int4 r = __ldg(&rows4[t]);               // default: placeB re-reads rows
    int k0 = atomicAdd(&g_count[r.x], 1);
    int k1 = atomicAdd(&g_count[r.y], 1);
    int k2 = atomicAdd(&g_count[r.z], 1);
    int k3 = atomicAdd(&g_count[r.w], 1);
    *reinterpret_cast<int4*>(&g_rank[t * 4]) = make_int4(k0, k1, k2, k3);  // hot
}

__global__ void __launch_bounds__(256) rank_tail_kernel(
    const int* __restrict__ rows, int start, int n_edges)
{
    int e = start + blockIdx.x * blockDim.x + threadIdx.x;
    if (e < n_edges) g_rank[e] = atomicAdd(&g_count[rows[e]], 1);
}

// ---- 2) single-pass decoupled-lookback exclusive scan ----
__global__ void __launch_bounds__(SCAN_BS) scan_kernel(int n_nodes, int n_edges) {
    __shared__ int warp_sums[16];
    __shared__ int s_excl;
    int b    = blockIdx.x;
    int tid  = threadIdx.x;
    int lane = tid & 31;
    int wid  = tid >> 5;
    int g    = b * SCAN_BS + tid;

    int v = 0;
    if (g < n_nodes) {
        v = g_count[g];
        g_count[g] = 0;                      // invariant for next replay
    }

    int incl = v;
    #pragma unroll
    for (int o = 1; o < 32; o <<= 1) {
        int n = __shfl_up_sync(0xffffffffu, incl, o);
        if (lane >= o) incl += n;
    }
    if (lane == 31) warp_sums[wid] = incl;
    __syncthreads();

    if (wid == 0) {
        int ws = (lane < 16) ? warp_sums[lane] : 0;
        #pragma unroll
        for (int o = 1; o < 32; o <<= 1) {
            int n = __shfl_up_sync(0xffffffffu, ws, o);
            if (lane >= o) ws += n;
        }
        if (lane < 16) warp_sums[lane] = ws;
    }
    __syncthreads();

    int block_total = warp_sums[15];
    int thread_excl = ((wid == 0) ? 0 : warp_sums[wid - 1]) + incl - v;

    if (wid == 0) {
        int sum = 0;
        if (b == 0) {
            if (lane == 0)
                st_rel_u64(&g_desc[0], (2ULL << 32) | (unsigned)block_total);
        } else {
            if (lane == 0)
                st_rel_u64(&g_desc[b], (1ULL << 32) | (unsigned)block_total);
            int base = b;
            bool done = false;
            while (!done) {
                int idx = base - 32 + lane;
                unsigned f = 1;
                int val = 0;
                if (idx >= 0) {
                    unsigned long long dd;
                    do {
                        dd = ld_rel_u64(&g_desc[idx]);
                        f = (unsigned)(dd >> 32);
                    } while (f == 0);
                    val = (int)(unsigned)dd;
                }
                unsigned m2 = __ballot_sync(0xffffffffu, f == 2u);
                int P = m2 ? (31 - __clz(m2)) : -1;
                if (P >= 0 && lane < P) val = 0;
                #pragma unroll
                for (int o = 16; o; o >>= 1)
                    val += __shfl_xor_sync(0xffffffffu, val, o);
                sum += val;
                if (P >= 0) done = true; else base -= 32;
            }
            if (lane == 0)
                st_rel_u64(&g_desc[b], (2ULL << 32) | (unsigned)(sum + block_total));
        }
        if (lane == 0) s_excl = sum;
    }
    __syncthreads();

    int excl = s_excl;
    if (g < n_nodes) g_rowstart[g] = excl + thread_excl;
    if (b == 0 && tid == 0) g_rowstart[n_nodes] = n_edges;
}

// ---- 3) placeB: atomic-free scatter; stores PRE-SCALED col*16 ----
__global__ void __launch_bounds__(256) placeB_kernel(
    const int4*   __restrict__ rows4,
    const int4*   __restrict__ cols4,
    const float4* __restrict__ vals4,
    int n_quads)
{
    int t = blockIdx.x * blockDim.x + threadIdx.x;
    if (t < NB) g_desc[t] = 0;               // reset lookback state for next replay
    if (t >= n_quads) return;

    int4   r = ldcs_int4(&rows4[t]);         // last touch
    int4   c = ldcs_int4(&cols4[t]);         // last touch
    float4 v = ldcs_float4(&vals4[t]);       // last touch
    int4   k = ldcs_int4(reinterpret_cast<const int4*>(&g_rank[t * 4]));  // last touch

    int s0 = __ldg(&g_rowstart[r.x]);
    int s1 = __ldg(&g_rowstart[r.y]);
    int s2 = __ldg(&g_rowstart[r.z]);
    int s3 = __ldg(&g_rowstart[r.w]);

    g_edge[s0 + k.x] = make_int2(c.x << 4, __float_as_int(v.x));   // col*16
    g_edge[s1 + k.y] = make_int2(c.y << 4, __float_as_int(v.y));
    g_edge[s2 + k.z] = make_int2(c.z << 4, __float_as_int(v.z));
    g_edge[s3 + k.w] = make_int2(c.w << 4, __float_as_int(v.w));
}

__global__ void __launch_bounds__(256) placeB_tail_kernel(
    const int*   __restrict__ rows,
    const int*   __restrict__ cols,
    const float* __restrict__ vals,
    int start, int n_edges)
{
    int e = start + blockIdx.x * blockDim.x + threadIdx.x;
    if (e >= n_edges) return;
    int r = rows[e];
    int pos = __ldg(&g_rowstart[r]) + g_rank[e];
    g_edge[pos] = make_int2(cols[e] << 4, __float_as_int(vals[e]));
}

// ---- 4) aggregate: 2 nodes per warp, 16-lane halves, float4 lanes ----
__global__ void __launch_bounds__(256) aggregate_kernel(
    const float4* __restrict__ embeds4,   // [NV, 16] float4
    float4*       __restrict__ out4,      // [NV, 16] float4
    int n_nodes)
{
    int warp = (blockIdx.x * blockDim.x + threadIdx.x) >> 5;
    int lane = threadIdx.x & 31;
    int half = lane >> 4;                 // 0 or 1
    int sub  = lane & 15;                 // float4 index within row

    int node = warp * 2 + half;
    if (node >= n_nodes) return;

    int i   = g_rowstart[node];
    int end = g_rowstart[node + 1];

    const float4* eb = embeds4 + sub;     // lane offset hoisted

    float4 acc = make_float4(0.f, 0.f, 0.f, 0.f);

    for (; i + 1 < end; i += 2) {         // 2 edges per half per iteration
        int2 p0 = __ldg(&g_edge[i]);
        int2 p1 = __ldg(&g_edge[i + 1]);
        float4 x0 = __ldg(eb + p0.x);     // p0.x = col*16 (pre-scaled)
        float4 x1 = __ldg(eb + p1.x);
        float v0 = __int_as_float(p0.y);
        float v1 = __int_as_float(p1.y);
        acc.x += v0 * x0.x; acc.y += v0 * x0.y;
        acc.z += v0 * x0.z; acc.w += v0 * x0.w;
        acc.x += v1 * x1.x; acc.y += v1 * x1.y;
        acc.z += v1 * x1.z; acc.w += v1 * x1.w;
    }
    if (i < end) {
        int2 p = __ldg(&g_edge[i]);
        float4 x = __ldg(eb + p.x);
        float v = __int_as_float(p.y);
        acc.x += v * x.x; acc.y += v * x.y;
        acc.z += v * x.z; acc.w += v * x.w;
    }
    stcs_float4(&out4[(size_t)node * 16 + sub], acc);   // last touch
}

extern "C" void kernel_launch(void* const* d_in, const int* in_sizes, int n_in,
                              void* d_out, int out_size)
{
    const int*   rows   = (const int*)d_in[0];
    const int*   cols   = (const int*)d_in[1];
    const float* vals   = (const float*)d_in[2];
    const float* embeds = (const float*)d_in[3];
    int n_edges = in_sizes[0];
    if (n_edges > NE) n_edges = NE;
    int n_nodes = out_size / D_FEAT;
    if (n_nodes > NV) n_nodes = NV;

    float* out = (float*)d_out;

    int n_quads   = n_edges >> 2;
    int quad_tail = n_quads << 2;

    {   // 1) rank
        int blocks = (n_quads + 255) / 256;
        rank_kernel<<<blocks, 256>>>((const int4*)rows, n_quads);
        if (quad_tail < n_edges) {
            int tail = n_edges - quad_tail;
            rank_tail_kernel<<<(tail + 255) / 256, 256>>>(rows, quad_tail, n_edges);
        }
    }
    {   // 2) single-pass scan
        scan_kernel<<<NB, SCAN_BS>>>(n_nodes, n_edges);
    }
    {   // 3) placeB
        int blocks = (n_quads + 255) / 256;
        placeB_kernel<<<blocks, 256>>>(
            (const int4*)rows, (const int4*)cols, (const float4*)vals, n_quads);
        if (quad_tail < n_edges) {
            int tail = n_edges - quad_tail;
            placeB_tail_kernel<<<(tail + 255) / 256, 256>>>(
                rows, cols, vals, quad_tail, n_edges);
        }
    }
    {   // 4) aggregate: one warp per TWO nodes
        int n_warps = (n_nodes + 1) / 2;
        long long total = (long long)n_warps * 32;
        int blocks = (int)((total + 255) / 256);
        aggregate_kernel<<<blocks, 256>>>(
            (const float4*)embeds, (float4*)out, n_nodes);
    }
}

// round 16
// speedup vs baseline: 1.0838x; 1.0253x over previous
#include <cuda_runtime.h>
#include <cuda_bf16.h>
#include <cstdint>

// GCN sparse aggregation: out[r,:] += vals[e] * embeds[cols[e],:]
// N=100000 nodes, E=1600000 edges, D=64, fp32.
//
// Round 15: r14 pipeline (best @74.0) with a deeper-MLP aggregate:
//   2 nodes per warp (16-lane halves, float4 lanes) + UNROLL 4 edges per
//   iteration -> 4 independent edge loads + 4 independent gathers in flight
//   per half (fixes the dependent-latency regime seen at r14: issue 26%,
//   L2 44%, occ 61% -- nothing saturated).
// Pipeline: rank (+desc reset) -> lookback scan -> placeB -> aggregate.

#define D_FEAT 64
#define NV 100000
#define NE 1600000
#define SCAN_BS 512
#define NB ((NV + SCAN_BS - 1) / SCAN_BS)   // 196

__device__ int  g_count[NV];        // zero at load; scan restores 0 each run
__device__ int  g_rowstart[NV + 1];
__device__ int  g_rank[NE];
__device__ int2 g_edge[NE];         // {col*16, val_bits}, grouped by row
__device__ unsigned long long g_desc[NB];   // lookback {flag,value}; rank resets

// ---- memory helpers ----
__device__ __forceinline__ int4 ldcs_int4(const int4* p) {
    int4 v;
    asm volatile("ld.global.cs.v4.s32 {%0,%1,%2,%3}, [%4];"
                 : "=r"(v.x), "=r"(v.y), "=r"(v.z), "=r"(v.w) : "l"(p));
    return v;
}
__device__ __forceinline__ float4 ldcs_float4(const float4* p) {
    float4 v;
    asm volatile("ld.global.cs.v4.f32 {%0,%1,%2,%3}, [%4];"
                 : "=f"(v.x), "=f"(v.y), "=f"(v.z), "=f"(v.w) : "l"(p));
    return v;
}
__device__ __forceinline__ void stcs_float4(float4* p, float4 v) {
    asm volatile("st.global.cs.v4.f32 [%0], {%1,%2,%3,%4};"
                 :: "l"(p), "f"(v.x), "f"(v.y), "f"(v.z), "f"(v.w) : "memory");
}
__device__ __forceinline__ void st_rel_u64(unsigned long long* p, unsigned long long v) {
    asm volatile("st.relaxed.gpu.global.u64 [%0], %1;" :: "l"(p), "l"(v) : "memory");
}
__device__ __forceinline__ unsigned long long ld_rel_u64(const unsigned long long* p) {
    unsigned long long v;
    asm volatile("ld.relaxed.gpu.global.u64 %0, [%1];" : "=l"(v) : "l"(p) : "memory");
    return v;
}

// ---- 1) rank: histogram + slot assignment (+ desc reset for scan) ----
__global__ void __launch_bounds__(256) rank_kernel(
    const int4* __restrict__ rows4, int n_quads)
{
    int t = blockIdx.x * blockDim.x + threadIdx.x;
    if (t < NB) g_desc[t] = 0;                // reset lookback state (pre-scan)
    if (t >= n_quads) return;
    int4 r = __ldg(&rows4[t]);                // default: placeB re-reads rows
    int k0 = atomicAdd(&g_count[r.x], 1);
    int k1 = atomicAdd(&g_count[r.y], 1);
    int k2 = atomicAdd(&g_count[r.z], 1);
    int k3 = atomicAdd(&g_count[r.w], 1);
    *reinterpret_cast<int4*>(&g_rank[t * 4]) = make_int4(k0, k1, k2, k3);  // hot
}

__global__ void __launch_bounds__(256) rank_tail_kernel(
    const int* __restrict__ rows, int start, int n_edges)
{
    int e = start + blockIdx.x * blockDim.x + threadIdx.x;
    if (e < n_edges) g_rank[e] = atomicAdd(&g_count[rows[e]], 1);
}

// ---- 2) single-pass decoupled-lookback exclusive scan ----
__global__ void __launch_bounds__(SCAN_BS) scan_kernel(int n_nodes, int n_edges) {
    __shared__ int warp_sums[16];
    __shared__ int s_excl;
    int b    = blockIdx.x;
    int tid  = threadIdx.x;
    int lane = tid & 31;
    int wid  = tid >> 5;
    int g    = b * SCAN_BS + tid;

    int v = 0;
    if (g < n_nodes) {
        v = g_count[g];
        g_count[g] = 0;                      // invariant for next replay
    }

    int incl = v;
    #pragma unroll
    for (int o = 1; o < 32; o <<= 1) {
        int n = __shfl_up_sync(0xffffffffu, incl, o);
        if (lane >= o) incl += n;
    }
    if (lane == 31) warp_sums[wid] = incl;
    __syncthreads();

    if (wid == 0) {
        int ws = (lane < 16) ? warp_sums[lane] : 0;
        #pragma unroll
        for (int o = 1; o < 32; o <<= 1) {
            int n = __shfl_up_sync(0xffffffffu, ws, o);
            if (lane >= o) ws += n;
        }
        if (lane < 16) warp_sums[lane] = ws;
    }
    __syncthreads();

    int block_total = warp_sums[15];
    int thread_excl = ((wid == 0) ? 0 : warp_sums[wid - 1]) + incl - v;

    if (wid == 0) {
        int sum = 0;
        if (b == 0) {
            if (lane == 0)
                st_rel_u64(&g_desc[0], (2ULL << 32) | (unsigned)block_total);
        } else {
            if (lane == 0)
                st_rel_u64(&g_desc[b], (1ULL << 32) | (unsigned)block_total);
            int base = b;
            bool done = false;
            while (!done) {
                int idx = base - 32 + lane;
                unsigned f = 1;
                int val = 0;
                if (idx >= 0) {
                    unsigned long long dd;
                    do {
                        dd = ld_rel_u64(&g_desc[idx]);
                        f = (unsigned)(dd >> 32);
                    } while (f == 0);
                    val = (int)(unsigned)dd;
                }
                unsigned m2 = __ballot_sync(0xffffffffu, f == 2u);
                int P = m2 ? (31 - __clz(m2)) : -1;
                if (P >= 0 && lane < P) val = 0;
                #pragma unroll
                for (int o = 16; o; o >>= 1)
                    val += __shfl_xor_sync(0xffffffffu, val, o);
                sum += val;
                if (P >= 0) done = true; else base -= 32;
            }
            if (lane == 0)
                st_rel_u64(&g_desc[b], (2ULL << 32) | (unsigned)(sum + block_total));
        }
        if (lane == 0) s_excl = sum;
    }
    __syncthreads();

    int excl = s_excl;
    if (g < n_nodes) g_rowstart[g] = excl + thread_excl;
    if (b == 0 && tid == 0) g_rowstart[n_nodes] = n_edges;
}

// ---- 3) placeB: atomic-free scatter; stores PRE-SCALED col*16 ----
__global__ void __launch_bounds__(256) placeB_kernel(
    const int4*   __restrict__ rows4,
    const int4*   __restrict__ cols4,
    const float4* __restrict__ vals4,
    int n_quads)
{
    int t = blockIdx.x * blockDim.x + threadIdx.x;
    if (t >= n_quads) return;

    int4   r = ldcs_int4(&rows4[t]);         // last touch
    int4   c = ldcs_int4(&cols4[t]);         // last touch
    float4 v = ldcs_float4(&vals4[t]);       // last touch
    int4   k = ldcs_int4(reinterpret_cast<const int4*>(&g_rank[t * 4]));  // last touch

    int s0 = __ldg(&g_rowstart[r.x]);
    int s1 = __ldg(&g_rowstart[r.y]);
    int s2 = __ldg(&g_rowstart[r.z]);
    int s3 = __ldg(&g_rowstart[r.w]);

    g_edge[s0 + k.x] = make_int2(c.x << 4, __float_as_int(v.x));   // col*16
    g_edge[s1 + k.y] = make_int2(c.y << 4, __float_as_int(v.y));
    g_edge[s2 + k.z] = make_int2(c.z << 4, __float_as_int(v.z));
    g_edge[s3 + k.w] = make_int2(c.w << 4, __float_as_int(v.w));
}

__global__ void __launch_bounds__(256) placeB_tail_kernel(
    const int*   __restrict__ rows,
    const int*   __restrict__ cols,
    const float* __restrict__ vals,
    int start, int n_edges)
{
    int e = start + blockIdx.x * blockDim.x + threadIdx.x;
    if (e >= n_edges) return;
    int r = rows[e];
    int pos = __ldg(&g_rowstart[r]) + g_rank[e];
    g_edge[pos] = make_int2(cols[e] << 4, __float_as_int(vals[e]));
}

// ---- 4) aggregate: 2 nodes/warp, float4 lanes, UNROLL 4 (MLP=4) ----
__global__ void __launch_bounds__(256) aggregate_kernel(
    const float4* __restrict__ embeds4,   // [NV, 16] float4
    float4*       __restrict__ out4,      // [NV, 16] float4
    int n_nodes)
{
    int warp = (blockIdx.x * blockDim.x + threadIdx.x) >> 5;
    int lane = threadIdx.x & 31;
    int half = lane >> 4;                 // 0 or 1
    int sub  = lane & 15;                 // float4 index within row

    int node = warp * 2 + half;
    if (node >= n_nodes) return;

    int i   = g_rowstart[node];
    int end = g_rowstart[node + 1];

    const float4* eb = embeds4 + sub;     // lane offset hoisted

    float4 acc = make_float4(0.f, 0.f, 0.f, 0.f);

    for (; i + 3 < end; i += 4) {         // 4 edges per half per iteration
        int2 p0 = __ldg(&g_edge[i]);
        int2 p1 = __ldg(&g_edge[i + 1]);
        int2 p2 = __ldg(&g_edge[i + 2]);
        int2 p3 = __ldg(&g_edge[i + 3]);
        float4 x0 = __ldg(eb + p0.x);     // pre-scaled col*16
        float4 x1 = __ldg(eb + p1.x);
        float4 x2 = __ldg(eb + p2.x);
        float4 x3 = __ldg(eb + p3.x);
        float v0 = __int_as_float(p0.y);
        float v1 = __int_as_float(p1.y);
        float v2 = __int_as_float(p2.y);
        float v3 = __int_as_float(p3.y);
        acc.x += v0 * x0.x; acc.y += v0 * x0.y;
        acc.z += v0 * x0.z; acc.w += v0 * x0.w;
        acc.x += v1 * x1.x; acc.y += v1 * x1.y;
        acc.z += v1 * x1.z; acc.w += v1 * x1.w;
        acc.x += v2 * x2.x; acc.y += v2 * x2.y;
        acc.z += v2 * x2.z; acc.w += v2 * x2.w;
        acc.x += v3 * x3.x; acc.y += v3 * x3.y;
        acc.z += v3 * x3.z; acc.w += v3 * x3.w;
    }
    for (; i < end; ++i) {
        int2 p = __ldg(&g_edge[i]);
        float4 x = __ldg(eb + p.x);
        float v = __int_as_float(p.y);
        acc.x += v * x.x; acc.y += v * x.y;
        acc.z += v * x.z; acc.w += v * x.w;
    }
    stcs_float4(&out4[(size_t)node * 16 + sub], acc);   // last touch
}

extern "C" void kernel_launch(void* const* d_in, const int* in_sizes, int n_in,
                              void* d_out, int out_size)
{
    const int*   rows   = (const int*)d_in[0];
    const int*   cols   = (const int*)d_in[1];
    const float* vals   = (const float*)d_in[2];
    const float* embeds = (const float*)d_in[3];
    int n_edges = in_sizes[0];
    if (n_edges > NE) n_edges = NE;
    int n_nodes = out_size / D_FEAT;
    if (n_nodes > NV) n_nodes = NV;

    float* out = (float*)d_out;

    int n_quads   = n_edges >> 2;
    int quad_tail = n_quads << 2;

    {   // 1) rank (+ desc reset)
        int blocks = (n_quads + 255) / 256;
        rank_kernel<<<blocks, 256>>>((const int4*)rows, n_quads);
        if (quad_tail < n_edges) {
            int tail = n_edges - quad_tail;
            rank_tail_kernel<<<(tail + 255) / 256, 256>>>(rows, quad_tail, n_edges);
        }
    }
    {   // 2) single-pass scan
        scan_kernel<<<NB, SCAN_BS>>>(n_nodes, n_edges);
    }
    {   // 3) placeB
        int blocks = (n_quads + 255) / 256;
        placeB_kernel<<<blocks, 256>>>(
            (const int4*)rows, (const int4*)cols, (const float4*)vals, n_quads);
        if (quad_tail < n_edges) {
            int tail = n_edges - quad_tail;
            placeB_tail_kernel<<<(tail + 255) / 256, 256>>>(
                rows, cols, vals, quad_tail, n_edges);
        }
    }
    {   // 4) aggregate: one warp per TWO nodes
        int n_warps = (n_nodes + 1) / 2;
        long long total = (long long)n_warps * 32;
        int blocks = (int)((total + 255) / 256);
        aggregate_kernel<<<blocks, 256>>>(
            (const float4*)embeds, (float4*)out, n_nodes);
    }
}